// round 5
// baseline (speedup 1.0000x reference)
#include <cuda_runtime.h>
#include <math.h>

// Problem dims
#define Bsz 8
#define Lsz 128
#define Hsz 512
#define Vsz 32000
#define NROWS (Bsz * Lsz)        // 1024
#define PROB_ELEMS ((long)NROWS * Vsz)   // 32768000

// ---------------- scratch (single __device__ global, offsets in floats) ---
#define OFF_EMB      0
#define OFF_SATTN    (OFF_EMB + NROWS * Hsz)          // 524288
#define OFF_ATTNAPP  (OFF_SATTN + NROWS * Lsz)        // +131072
#define OFF_X        (OFF_ATTNAPP + NROWS * Hsz)
#define OFF_GI       (OFF_X + NROWS * Hsz)
#define OFF_GRUOUT   (OFF_GI + NROWS * 3 * Hsz)
#define OFF_CTX      (OFF_GRUOUT + NROWS * Hsz)
#define OFF_MIX      (OFF_CTX + Bsz * Hsz)
#define OFF_HGLOB    (OFF_MIX + NROWS)
#define OFF_BAR      (OFF_HGLOB + 2 * Bsz * Hsz)
#define SCRATCH_TOTAL (OFF_BAR + 32)

__device__ float d_scratch[SCRATCH_TOTAL];

// ---------------- embedding gather ---------------------------------------
__global__ void gather_kernel(const int* __restrict__ toks,
                              const float* __restrict__ emb,
                              float* __restrict__ out) {
    int row = blockIdx.x;
    int tok = toks[row];
    const float4* s = (const float4*)(emb + (long)tok * Hsz);
    float4* d = (float4*)(out + (long)row * Hsz);
    d[threadIdx.x] = s[threadIdx.x];   // 128 threads * float4 = 512 floats
}

// ---------------- generic SGEMM: C = A * B^T (A: MxK, B: NxK row-major) ---
// Requires M%64==0, N%64==0, K%16==0. flags: 1=accumulate C, 2=bias[n], 4=relu
#define FLAG_ACCUM 1
#define FLAG_BIAS  2
#define FLAG_RELU  4

__global__ void sgemm_tn_kernel(const float* __restrict__ A, int lda,
                                const float* __restrict__ B, int ldb,
                                float* __restrict__ C, int ldc,
                                int K, const float* __restrict__ bias, int flags) {
    __shared__ float As[16][68];
    __shared__ float Bs[16][68];
    const int bm = blockIdx.y * 64;
    const int bn = blockIdx.x * 64;
    const int tid = threadIdx.x;        // 256
    const int tx = tid & 15;
    const int ty = tid >> 4;
    const int lrow = tid >> 2;          // 0..63
    const int lk = (tid & 3) << 2;      // 0,4,8,12

    float acc00=0,acc01=0,acc02=0,acc03=0;
    float acc10=0,acc11=0,acc12=0,acc13=0;
    float acc20=0,acc21=0,acc22=0,acc23=0;
    float acc30=0,acc31=0,acc32=0,acc33=0;

    const float* Aptr = A + (long)(bm + lrow) * lda + lk;
    const float* Bptr = B + (long)(bn + lrow) * ldb + lk;

    for (int kt = 0; kt < K; kt += 16) {
        float4 a4 = *(const float4*)(Aptr + kt);
        float4 b4 = *(const float4*)(Bptr + kt);
        As[lk + 0][lrow] = a4.x; As[lk + 1][lrow] = a4.y;
        As[lk + 2][lrow] = a4.z; As[lk + 3][lrow] = a4.w;
        Bs[lk + 0][lrow] = b4.x; Bs[lk + 1][lrow] = b4.y;
        Bs[lk + 2][lrow] = b4.z; Bs[lk + 3][lrow] = b4.w;
        __syncthreads();
        #pragma unroll
        for (int k = 0; k < 16; k++) {
            float a0 = As[k][ty*4+0], a1 = As[k][ty*4+1];
            float a2 = As[k][ty*4+2], a3 = As[k][ty*4+3];
            float b0 = Bs[k][tx*4+0], b1 = Bs[k][tx*4+1];
            float b2 = Bs[k][tx*4+2], b3 = Bs[k][tx*4+3];
            acc00 += a0*b0; acc01 += a0*b1; acc02 += a0*b2; acc03 += a0*b3;
            acc10 += a1*b0; acc11 += a1*b1; acc12 += a1*b2; acc13 += a1*b3;
            acc20 += a2*b0; acc21 += a2*b1; acc22 += a2*b2; acc23 += a2*b3;
            acc30 += a3*b0; acc31 += a3*b1; acc32 += a3*b2; acc33 += a3*b3;
        }
        __syncthreads();
    }

    float accs[4][4] = {{acc00,acc01,acc02,acc03},{acc10,acc11,acc12,acc13},
                        {acc20,acc21,acc22,acc23},{acc30,acc31,acc32,acc33}};
    #pragma unroll
    for (int i = 0; i < 4; i++) {
        int m = bm + ty*4 + i;
        #pragma unroll
        for (int j = 0; j < 4; j++) {
            int n = bn + tx*4 + j;
            float v = accs[i][j];
            long idx = (long)m * ldc + n;
            if (flags & FLAG_ACCUM) v += C[idx];
            if (flags & FLAG_BIAS)  v += bias[n];
            if (flags & FLAG_RELU)  v = fmaxf(v, 0.0f);
            C[idx] = v;
        }
    }
}

// ---------------- attention softmax over axis=1 (over i, per (b,j)) ------
__global__ void attn_softmax_kernel(const float* __restrict__ S,
                                    float* __restrict__ W) {
    int b = blockIdx.x;          // 8 blocks
    int j = threadIdx.x;         // 128 threads
    const float* p = S + (long)b * Lsz * Lsz + j;
    float m = -1e30f;
    for (int i = 0; i < Lsz; i++) m = fmaxf(m, p[i * Lsz]);
    float s = 0.0f;
    for (int i = 0; i < Lsz; i++) s += expf(p[i * Lsz] - m);
    float inv = 1.0f / s;
    float* w = W + (long)b * Lsz * Lsz + j;
    for (int i = 0; i < Lsz; i++) w[i * Lsz] = expf(p[i * Lsz] - m) * inv;
}

// ---------------- attn_applied[b,i,:] = sum_j W[b,i,j] * E[b,j,:] --------
__global__ void attn_applied_kernel(const float* __restrict__ attnw,
                                    const float* __restrict__ enc_out,
                                    float* __restrict__ out) {
    int row = blockIdx.x;        // b*128 + i
    int b = row >> 7;
    __shared__ float w[Lsz];
    int tid = threadIdx.x;       // 128
    w[tid] = attnw[(long)row * Lsz + tid];
    __syncthreads();
    float a0 = 0, a1 = 0, a2 = 0, a3 = 0;
    const float* E = enc_out + (long)b * Lsz * Hsz;
    for (int j = 0; j < Lsz; j++) {
        float a = w[j];
        const float* er = E + j * Hsz;
        a0 += a * er[tid];       a1 += a * er[tid + 128];
        a2 += a * er[tid + 256]; a3 += a * er[tid + 384];
    }
    float* o = out + (long)row * Hsz;
    o[tid] = a0; o[tid + 128] = a1; o[tid + 256] = a2; o[tid + 384] = a3;
}

// ---------------- GRU: persistent cooperative kernel ----------------------
// 64 blocks, each owns 8 hidden indices j (all 3 gates, all 8 batches).
// Whh slice cached in SMEM; h exchanged via double-buffered global + barrier.
#define GRU_BLOCKS 64
#define GRU_THREADS 128

__global__ void reset_bar_kernel(unsigned* bar) { *bar = 0u; }

__global__ void gru_kernel(const float* __restrict__ Whh,
                           const float* __restrict__ bhh,
                           const float* __restrict__ gi,
                           const float* __restrict__ h0,
                           float* __restrict__ out,
                           float* __restrict__ hglob,
                           unsigned* __restrict__ bar) {
    extern __shared__ float sm[];
    float* wr = sm;                  // 8*512
    float* wz = sm + 8 * Hsz;
    float* wn = sm + 16 * Hsz;
    float* hh = sm + 24 * Hsz;       // 8 batches * 512

    const int blk = blockIdx.x;
    const int tid = threadIdx.x;     // 128

    // load Whh slice: rows {j, 512+j, 1024+j} for j in [blk*8, blk*8+8)
    for (int f = tid; f < 3072; f += GRU_THREADS) {   // 3072 float4 = 12288 floats
        int rowid = f >> 7;          // 0..23
        int k4 = f & 127;
        int g = rowid >> 3;
        int jl = rowid & 7;
        float4 v = *(const float4*)(Whh + (long)((g << 9) + (blk << 3) + jl) * Hsz + (k4 << 2));
        float* dst = (g == 0 ? wr : (g == 1 ? wz : wn)) + (jl << 9) + (k4 << 2);
        *(float4*)dst = v;
    }
    // load h0 into smem (all 8 batches)
    for (int f = tid; f < 1024; f += GRU_THREADS)
        ((float4*)hh)[f] = ((const float4*)h0)[f];
    __syncthreads();

    const int q  = tid & 3;            // k-quarter
    const int jl = (tid >> 2) & 7;
    const int bh = tid >> 5;           // 0..3 ; thread handles b=bh and b=bh+4
    const int j  = (blk << 3) + jl;

    const float bhr = bhh[j], bhz = bhh[Hsz + j], bhn = bhh[2 * Hsz + j];
    const float4* pwr = (const float4*)(wr + (jl << 9)) + (q << 5);
    const float4* pwz = (const float4*)(wz + (jl << 9)) + (q << 5);
    const float4* pwn = (const float4*)(wn + (jl << 9)) + (q << 5);
    const float4* ph0 = (const float4*)(hh + (bh << 9)) + (q << 5);
    const float4* ph1 = (const float4*)(hh + ((bh + 4) << 9)) + (q << 5);

    unsigned target = 0;

    for (int t = 0; t < Lsz; t++) {
        float ar0 = 0, az0 = 0, an0 = 0, ar1 = 0, az1 = 0, an1 = 0;
        #pragma unroll 4
        for (int i = 0; i < 32; i++) {
            float4 w4r = pwr[i], w4z = pwz[i], w4n = pwn[i];
            float4 hA = ph0[i], hB = ph1[i];
            ar0 += w4r.x*hA.x + w4r.y*hA.y + w4r.z*hA.z + w4r.w*hA.w;
            az0 += w4z.x*hA.x + w4z.y*hA.y + w4z.z*hA.z + w4z.w*hA.w;
            an0 += w4n.x*hA.x + w4n.y*hA.y + w4n.z*hA.z + w4n.w*hA.w;
            ar1 += w4r.x*hB.x + w4r.y*hB.y + w4r.z*hB.z + w4r.w*hB.w;
            az1 += w4z.x*hB.x + w4z.y*hB.y + w4z.z*hB.z + w4z.w*hB.w;
            an1 += w4n.x*hB.x + w4n.y*hB.y + w4n.z*hB.z + w4n.w*hB.w;
        }
        // reduce across the 4 k-quarters (adjacent lanes)
        #pragma unroll
        for (int off = 1; off <= 2; off <<= 1) {
            ar0 += __shfl_xor_sync(0xffffffffu, ar0, off);
            az0 += __shfl_xor_sync(0xffffffffu, az0, off);
            an0 += __shfl_xor_sync(0xffffffffu, an0, off);
            ar1 += __shfl_xor_sync(0xffffffffu, ar1, off);
            az1 += __shfl_xor_sync(0xffffffffu, az1, off);
            an1 += __shfl_xor_sync(0xffffffffu, an1, off);
        }
        if (q == 0) {
            #pragma unroll
            for (int half = 0; half < 2; half++) {
                int b = bh + (half ? 4 : 0);
                float ghr = half ? ar1 : ar0;
                float ghz = half ? az1 : az0;
                float ghn = half ? an1 : an0;
                long gbase = (long)((b << 7) + t) * (3 * Hsz);
                float ir = gi[gbase + j];
                float iz = gi[gbase + Hsz + j];
                float in_ = gi[gbase + 2 * Hsz + j];
                float r = 1.0f / (1.0f + expf(-(ir + ghr + bhr)));
                float z = 1.0f / (1.0f + expf(-(iz + ghz + bhz)));
                float n = tanhf(in_ + r * (ghn + bhn));
                float hold = hh[(b << 9) + j];
                float hnew = (1.0f - z) * n + z * hold;
                out[(long)((b << 7) + t) * Hsz + j] = hnew;
                hglob[((t + 1) & 1) * (Bsz * Hsz) + (b << 9) + j] = hnew;
            }
        }
        __threadfence();
        __syncthreads();
        if (tid == 0) {
            atomicAdd(bar, 1u);
            target += GRU_BLOCKS;
            volatile unsigned* vb = bar;
            while (*vb < target) { }
        }
        __syncthreads();
        __threadfence();
        // reload full h for next step (bypass L1 — other SMs wrote it)
        const float4* src = (const float4*)(hglob + ((t + 1) & 1) * (Bsz * Hsz));
        for (int f = tid; f < 1024; f += GRU_THREADS)
            ((float4*)hh)[f] = __ldcg(src + f);
        __syncthreads();
    }
}

// ---------------- copy-attention context (alphas independent of i) -------
__global__ void copy_ctx_kernel(const float* __restrict__ enc_out,
                                const int* __restrict__ enc_in,
                                const float* __restrict__ copyW,
                                float* __restrict__ ctx) {
    __shared__ float4 we4[Hsz / 4];
    __shared__ float alpha[Lsz];
    __shared__ float rbuf[Lsz];
    int b = blockIdx.x, tid = threadIdx.x;   // 128 threads
    we4[tid] = ((const float4*)copyW)[tid];  // w_e = copy_W[0:512]
    __syncthreads();
    // e_part[j] for j = tid
    const float4* row = (const float4*)(enc_out + (long)(b * Lsz + tid) * Hsz);
    float s = 0.0f;
    for (int k = 0; k < Hsz / 4; k++) {
        float4 r = row[k], w = we4[k];
        s += r.x*w.x + r.y*w.y + r.z*w.z + r.w*w.w;
    }
    if (enc_in[b * Lsz + tid] == 0) s -= 1000.0f;
    rbuf[tid] = s; __syncthreads();
    for (int st = 64; st > 0; st >>= 1) {
        if (tid < st) rbuf[tid] = fmaxf(rbuf[tid], rbuf[tid + st]);
        __syncthreads();
    }
    float m = rbuf[0]; __syncthreads();
    float e = expf(s - m);
    rbuf[tid] = e; __syncthreads();
    for (int st = 64; st > 0; st >>= 1) {
        if (tid < st) rbuf[tid] += rbuf[tid + st];
        __syncthreads();
    }
    alpha[tid] = e / rbuf[0];
    __syncthreads();
    float a0 = 0, a1 = 0, a2 = 0, a3 = 0;
    const float* E = enc_out + (long)b * Lsz * Hsz;
    for (int jj = 0; jj < Lsz; jj++) {
        float a = alpha[jj];
        const float* er = E + jj * Hsz;
        a0 += a * er[tid];       a1 += a * er[tid + 128];
        a2 += a * er[tid + 256]; a3 += a * er[tid + 384];
    }
    float* o = ctx + (long)b * Hsz;
    o[tid] = a0; o[tid + 128] = a1; o[tid + 256] = a2; o[tid + 384] = a3;
}

// ---------------- mix gate ------------------------------------------------
__global__ void mix_kernel(const float* __restrict__ gruout,
                           const float* __restrict__ ctx,
                           const float* __restrict__ emb,
                           const float* __restrict__ dgW,
                           const float* __restrict__ dgb,
                           float* __restrict__ mixbuf) {
    int row = blockIdx.x;        // b*128+i
    int b = row >> 7;
    int tid = threadIdx.x;       // 128
    const float* g = gruout + (long)row * Hsz;
    const float* c = ctx + (long)b * Hsz;
    const float* e = emb + (long)row * Hsz;
    float s = 0.0f;
    for (int k = tid; k < Hsz; k += 128)
        s += g[k] * dgW[k] + c[k] * dgW[Hsz + k] + e[k] * dgW[2 * Hsz + k];
    __shared__ float rbuf[128];
    rbuf[tid] = s; __syncthreads();
    for (int st = 64; st > 0; st >>= 1) {
        if (tid < st) rbuf[tid] += rbuf[tid + st];
        __syncthreads();
    }
    if (tid == 0) mixbuf[row] = 1.0f / (1.0f + expf(-(rbuf[0] + dgb[0])));
}

// ---------------- final: softmax over V + pointer mix (in place) ---------
__global__ void softmax_mix_kernel(float* __restrict__ prob,
                                   const float* __restrict__ mixbuf,
                                   const int* __restrict__ enc_in) {
    int row = blockIdx.x;        // b*128+i
    int tid = threadIdx.x;       // 256
    float* p = prob + (long)row * Vsz;
    __shared__ float rbuf[256];
    float m = -1e30f;
    for (int v = tid; v < Vsz; v += 256) m = fmaxf(m, p[v]);
    rbuf[tid] = m; __syncthreads();
    for (int st = 128; st > 0; st >>= 1) {
        if (tid < st) rbuf[tid] = fmaxf(rbuf[tid], rbuf[tid + st]);
        __syncthreads();
    }
    m = rbuf[0]; __syncthreads();
    float s = 0.0f;
    for (int v = tid; v < Vsz; v += 256) s += expf(p[v] - m);
    rbuf[tid] = s; __syncthreads();
    for (int st = 128; st > 0; st >>= 1) {
        if (tid < st) rbuf[tid] += rbuf[tid + st];
        __syncthreads();
    }
    float S = rbuf[0];
    float mix = mixbuf[row];
    float inv = mix / S;
    float add = 1.0f - mix;      // row_sum == 1 (softmax row sum)
    int tok = enc_in[row];
    for (int v = tid; v < Vsz; v += 256) {
        float pv = expf(p[v] - m) * inv;
        if (v == tok) pv += add;
        p[v] = pv;
    }
}

// ---------------- launch --------------------------------------------------
extern "C" void kernel_launch(void* const* d_in, const int* in_sizes, int n_in,
                              void* d_out, int out_size) {
    (void)in_sizes; (void)n_in; (void)out_size;
    const int*   input_   = (const int*)d_in[0];
    const int*   enc_in   = (const int*)d_in[1];
    const float* enc_hid  = (const float*)d_in[2];   // (1,B,H) -> h0
    const float* enc_out  = (const float*)d_in[3];
    const float* emb_tab  = (const float*)d_in[4];
    const float* attn_W   = (const float*)d_in[5];
    // d_in[6] attn_b: cancels in axis=1 softmax
    const float* comb_W   = (const float*)d_in[7];
    const float* comb_b   = (const float*)d_in[8];
    const float* gru_Wih  = (const float*)d_in[9];
    const float* gru_Whh  = (const float*)d_in[10];
    const float* gru_bih  = (const float*)d_in[11];
    const float* gru_bhh  = (const float*)d_in[12];
    const float* out_W    = (const float*)d_in[13];
    const float* out_b    = (const float*)d_in[14];
    const float* dogen_W  = (const float*)d_in[15];
    const float* dogen_b  = (const float*)d_in[16];
    const float* copy_W   = (const float*)d_in[17];
    // d_in[18] copy_b: cancels in copy softmax

    float* out   = (float*)d_out;
    float* prob  = out;                       // (B,L,V)
    float* attnw = out + PROB_ELEMS;          // (B,L,L)

    float* sc = nullptr;
    cudaGetSymbolAddress((void**)&sc, d_scratch);
    float* emb     = sc + OFF_EMB;
    float* sattn   = sc + OFF_SATTN;
    float* attnapp = sc + OFF_ATTNAPP;
    float* xbuf    = sc + OFF_X;
    float* gibuf   = sc + OFF_GI;
    float* gruout  = sc + OFF_GRUOUT;
    float* ctx     = sc + OFF_CTX;
    float* mixb    = sc + OFF_MIX;
    float* hglob   = sc + OFF_HGLOB;
    unsigned* bar  = (unsigned*)(sc + OFF_BAR);

    const int gru_smem = (24 * Hsz + Bsz * Hsz) * (int)sizeof(float);  // 65536
    cudaFuncSetAttribute(gru_kernel, cudaFuncAttributeMaxDynamicSharedMemorySize, gru_smem);

    // 1. embedding gather
    gather_kernel<<<NROWS, 128>>>(input_, emb_tab, emb);
    // 2. attn logits (emb part only; h0/attn_b cancel): (1024 x 128)
    sgemm_tn_kernel<<<dim3(Lsz / 64, NROWS / 64), 256>>>(
        emb, Hsz, attn_W, 2 * Hsz, sattn, Lsz, Hsz, nullptr, 0);
    // 3. softmax over i -> attn_weights (output tail)
    attn_softmax_kernel<<<Bsz, Lsz>>>(sattn, attnw);
    // 4. attn_applied
    attn_applied_kernel<<<NROWS, 128>>>(attnw, enc_out, attnapp);
    // 5. comb: x = relu(emb@W1^T + attnapp@W2^T + b)
    sgemm_tn_kernel<<<dim3(Hsz / 64, NROWS / 64), 256>>>(
        emb, Hsz, comb_W, 2 * Hsz, xbuf, Hsz, Hsz, nullptr, 0);
    sgemm_tn_kernel<<<dim3(Hsz / 64, NROWS / 64), 256>>>(
        attnapp, Hsz, comb_W + Hsz, 2 * Hsz, xbuf, Hsz, Hsz, comb_b,
        FLAG_ACCUM | FLAG_BIAS | FLAG_RELU);
    // 6. gi = x @ Wih^T + bih  (1024 x 1536)
    sgemm_tn_kernel<<<dim3(3 * Hsz / 64, NROWS / 64), 256>>>(
        xbuf, Hsz, gru_Wih, Hsz, gibuf, 3 * Hsz, Hsz, gru_bih, FLAG_BIAS);
    // 7. GRU (persistent cooperative)
    reset_bar_kernel<<<1, 1>>>(bar);
    gru_kernel<<<GRU_BLOCKS, GRU_THREADS, gru_smem>>>(
        gru_Whh, gru_bhh, gibuf, enc_hid, gruout, hglob, bar);
    // 8. output logits GEMM (1024 x 32000) straight into d_out
    sgemm_tn_kernel<<<dim3(Vsz / 64, NROWS / 64), 256>>>(
        gruout, Hsz, out_W, Hsz, prob, Vsz, Hsz, out_b, FLAG_BIAS);
    // 9. copy-attention context (i-independent)
    copy_ctx_kernel<<<Bsz, Lsz>>>(enc_out, enc_in, copy_W, ctx);
    // 10. mix gate
    mix_kernel<<<NROWS, 128>>>(gruout, ctx, emb, dogen_W, dogen_b, mixb);
    // 11. softmax over V + pointer mix, in place
    softmax_mix_kernel<<<NROWS, 256>>>(prob, mixb, enc_in);
}

// round 6
// speedup vs baseline: 1.0556x; 1.0556x over previous
#include <cuda_runtime.h>
#include <math.h>

// Problem dims
#define Bsz 8
#define Lsz 128
#define Hsz 512
#define Vsz 32000
#define NROWS (Bsz * Lsz)        // 1024
#define PROB_ELEMS ((long)NROWS * Vsz)   // 32768000

// ---------------- scratch (single __device__ global, offsets in floats) ---
#define OFF_EMB      0
#define OFF_SATTN    (OFF_EMB + NROWS * Hsz)
#define OFF_ATTNAPP  (OFF_SATTN + NROWS * Lsz)
#define OFF_X        (OFF_ATTNAPP + NROWS * Hsz)
#define OFF_GI       (OFF_X + NROWS * Hsz)
#define OFF_GRUOUT   (OFF_GI + NROWS * 3 * Hsz)
#define OFF_CTX      (OFF_GRUOUT + NROWS * Hsz)
#define OFF_MIX      (OFF_CTX + Bsz * Hsz)
#define OFF_HGLOB    (OFF_MIX + NROWS)
#define OFF_BAR      (OFF_HGLOB + 2 * Bsz * Hsz)
#define SCRATCH_TOTAL (OFF_BAR + 32)

__device__ float d_scratch[SCRATCH_TOTAL];

// ---------------- embedding gather ---------------------------------------
__global__ void gather_kernel(const int* __restrict__ toks,
                              const float* __restrict__ emb,
                              float* __restrict__ out) {
    int row = blockIdx.x;
    int tok = toks[row];
    const float4* s = (const float4*)(emb + (long)tok * Hsz);
    float4* d = (float4*)(out + (long)row * Hsz);
    d[threadIdx.x] = s[threadIdx.x];
}

// ---------------- SGEMM 128x128x16, double-buffered, 8x8 per thread -------
// C = A * B^T ; A: MxK (lda), B: NxK (ldb), C: MxN (ldc)
// Requires M%128==0, N%128==0, K%16==0.
#define FLAG_ACCUM 1
#define FLAG_BIAS  2
#define FLAG_RELU  4

#define BM 128
#define BN 128
#define BK 16
#define SPAD 4   // row pad in floats (keeps 16B alignment: (128+4)*4=528=16*33)

__global__ __launch_bounds__(256)
void sgemm128_kernel(const float* __restrict__ A, int lda,
                     const float* __restrict__ B, int ldb,
                     float* __restrict__ C, int ldc,
                     int K, const float* __restrict__ bias, int flags) {
    __shared__ float As[2][BK][BM + SPAD];
    __shared__ float Bs[2][BK][BN + SPAD];

    const int tid = threadIdx.x;          // 256
    const int tx = tid & 15;              // N dir (0..15)
    const int ty = tid >> 4;              // M dir (0..15)
    const long bm = (long)blockIdx.y * BM;
    const long bn = (long)blockIdx.x * BN;

    // global-load mapping: each tile is 128 rows x 16 cols = 512 float4;
    // thread handles float4 indices f=tid and f=tid+256. row=f>>2, koff=(f&3)*4
    const int r0 = tid >> 2;              // 0..63
    const int r1 = r0 + 64;               // 64..127
    const int kq = (tid & 3) << 2;        // 0,4,8,12

    const float* Ag = A + (bm + r0) * lda + kq;
    const float* Ag2 = A + (bm + r1) * lda + kq;
    const float* Bg = B + (bn + r0) * ldb + kq;
    const float* Bg2 = B + (bn + r1) * ldb + kq;

    float acc[8][8];
    #pragma unroll
    for (int i = 0; i < 8; i++)
        #pragma unroll
        for (int j = 0; j < 8; j++) acc[i][j] = 0.0f;

    // prefetch tile 0 into smem buffer 0
    {
        float4 a0 = *(const float4*)(Ag);
        float4 a1 = *(const float4*)(Ag2);
        float4 b0 = *(const float4*)(Bg);
        float4 b1 = *(const float4*)(Bg2);
        As[0][kq + 0][r0] = a0.x; As[0][kq + 1][r0] = a0.y;
        As[0][kq + 2][r0] = a0.z; As[0][kq + 3][r0] = a0.w;
        As[0][kq + 0][r1] = a1.x; As[0][kq + 1][r1] = a1.y;
        As[0][kq + 2][r1] = a1.z; As[0][kq + 3][r1] = a1.w;
        Bs[0][kq + 0][r0] = b0.x; Bs[0][kq + 1][r0] = b0.y;
        Bs[0][kq + 2][r0] = b0.z; Bs[0][kq + 3][r0] = b0.w;
        Bs[0][kq + 0][r1] = b1.x; Bs[0][kq + 1][r1] = b1.y;
        Bs[0][kq + 2][r1] = b1.z; Bs[0][kq + 3][r1] = b1.w;
    }
    __syncthreads();

    int buf = 0;
    const int T = K / BK;
    for (int t = 0; t < T; t++) {
        float4 a0, a1, b0, b1;
        const bool more = (t + 1 < T);
        if (more) {
            int kt = (t + 1) * BK;
            a0 = *(const float4*)(Ag + kt);
            a1 = *(const float4*)(Ag2 + kt);
            b0 = *(const float4*)(Bg + kt);
            b1 = *(const float4*)(Bg2 + kt);
        }

        #pragma unroll
        for (int k = 0; k < BK; k++) {
            float4 af0 = *(const float4*)&As[buf][k][ty * 8];
            float4 af1 = *(const float4*)&As[buf][k][ty * 8 + 4];
            float4 bf0 = *(const float4*)&Bs[buf][k][tx * 8];
            float4 bf1 = *(const float4*)&Bs[buf][k][tx * 8 + 4];
            float ar[8] = {af0.x, af0.y, af0.z, af0.w, af1.x, af1.y, af1.z, af1.w};
            float br[8] = {bf0.x, bf0.y, bf0.z, bf0.w, bf1.x, bf1.y, bf1.z, bf1.w};
            #pragma unroll
            for (int i = 0; i < 8; i++)
                #pragma unroll
                for (int j = 0; j < 8; j++)
                    acc[i][j] += ar[i] * br[j];
        }

        if (more) {
            int nb = buf ^ 1;
            As[nb][kq + 0][r0] = a0.x; As[nb][kq + 1][r0] = a0.y;
            As[nb][kq + 2][r0] = a0.z; As[nb][kq + 3][r0] = a0.w;
            As[nb][kq + 0][r1] = a1.x; As[nb][kq + 1][r1] = a1.y;
            As[nb][kq + 2][r1] = a1.z; As[nb][kq + 3][r1] = a1.w;
            Bs[nb][kq + 0][r0] = b0.x; Bs[nb][kq + 1][r0] = b0.y;
            Bs[nb][kq + 2][r0] = b0.z; Bs[nb][kq + 3][r0] = b0.w;
            Bs[nb][kq + 0][r1] = b1.x; Bs[nb][kq + 1][r1] = b1.y;
            Bs[nb][kq + 2][r1] = b1.z; Bs[nb][kq + 3][r1] = b1.w;
        }
        __syncthreads();
        buf ^= 1;
    }

    // epilogue
    #pragma unroll
    for (int i = 0; i < 8; i++) {
        long m = bm + ty * 8 + i;
        long n = bn + tx * 8;
        float* cp = C + m * ldc + n;
        float v[8];
        #pragma unroll
        for (int j = 0; j < 8; j++) v[j] = acc[i][j];
        if (flags & FLAG_ACCUM) {
            float4 c0 = *(float4*)(cp);
            float4 c1 = *(float4*)(cp + 4);
            v[0]+=c0.x; v[1]+=c0.y; v[2]+=c0.z; v[3]+=c0.w;
            v[4]+=c1.x; v[5]+=c1.y; v[6]+=c1.z; v[7]+=c1.w;
        }
        if (flags & FLAG_BIAS) {
            float4 bb0 = *(const float4*)(bias + n);
            float4 bb1 = *(const float4*)(bias + n + 4);
            v[0]+=bb0.x; v[1]+=bb0.y; v[2]+=bb0.z; v[3]+=bb0.w;
            v[4]+=bb1.x; v[5]+=bb1.y; v[6]+=bb1.z; v[7]+=bb1.w;
        }
        if (flags & FLAG_RELU) {
            #pragma unroll
            for (int j = 0; j < 8; j++) v[j] = fmaxf(v[j], 0.0f);
        }
        *(float4*)(cp)     = make_float4(v[0], v[1], v[2], v[3]);
        *(float4*)(cp + 4) = make_float4(v[4], v[5], v[6], v[7]);
    }
}

// ---------------- attention softmax over axis=1 (over i, per (b,j)) ------
__global__ void attn_softmax_kernel(const float* __restrict__ S,
                                    float* __restrict__ W) {
    int b = blockIdx.x;
    int j = threadIdx.x;
    const float* p = S + (long)b * Lsz * Lsz + j;
    float m = -1e30f;
    for (int i = 0; i < Lsz; i++) m = fmaxf(m, p[i * Lsz]);
    float s = 0.0f;
    for (int i = 0; i < Lsz; i++) s += expf(p[i * Lsz] - m);
    float inv = 1.0f / s;
    float* w = W + (long)b * Lsz * Lsz + j;
    for (int i = 0; i < Lsz; i++) w[i * Lsz] = expf(p[i * Lsz] - m) * inv;
}

// ---------------- attn_applied[b,i,:] = sum_j W[b,i,j] * E[b,j,:] --------
__global__ void attn_applied_kernel(const float* __restrict__ attnw,
                                    const float* __restrict__ enc_out,
                                    float* __restrict__ out) {
    int row = blockIdx.x;
    int b = row >> 7;
    __shared__ float w[Lsz];
    int tid = threadIdx.x;
    w[tid] = attnw[(long)row * Lsz + tid];
    __syncthreads();
    float a0 = 0, a1 = 0, a2 = 0, a3 = 0;
    const float* E = enc_out + (long)b * Lsz * Hsz;
    for (int j = 0; j < Lsz; j++) {
        float a = w[j];
        const float* er = E + j * Hsz;
        a0 += a * er[tid];       a1 += a * er[tid + 128];
        a2 += a * er[tid + 256]; a3 += a * er[tid + 384];
    }
    float* o = out + (long)row * Hsz;
    o[tid] = a0; o[tid + 128] = a1; o[tid + 256] = a2; o[tid + 384] = a3;
}

// ---------------- GRU: persistent cooperative kernel ----------------------
#define GRU_BLOCKS 64
#define GRU_THREADS 128

__global__ void reset_bar_kernel(unsigned* bar) { *bar = 0u; }

__global__ void gru_kernel(const float* __restrict__ Whh,
                           const float* __restrict__ bhh,
                           const float* __restrict__ gi,
                           const float* __restrict__ h0,
                           float* __restrict__ out,
                           float* __restrict__ hglob,
                           unsigned* __restrict__ bar) {
    extern __shared__ float sm[];
    float* wr = sm;
    float* wz = sm + 8 * Hsz;
    float* wn = sm + 16 * Hsz;
    float* hh = sm + 24 * Hsz;

    const int blk = blockIdx.x;
    const int tid = threadIdx.x;

    for (int f = tid; f < 3072; f += GRU_THREADS) {
        int rowid = f >> 7;
        int k4 = f & 127;
        int g = rowid >> 3;
        int jl = rowid & 7;
        float4 v = *(const float4*)(Whh + (long)((g << 9) + (blk << 3) + jl) * Hsz + (k4 << 2));
        float* dst = (g == 0 ? wr : (g == 1 ? wz : wn)) + (jl << 9) + (k4 << 2);
        *(float4*)dst = v;
    }
    for (int f = tid; f < 1024; f += GRU_THREADS)
        ((float4*)hh)[f] = ((const float4*)h0)[f];
    __syncthreads();

    const int q  = tid & 3;
    const int jl = (tid >> 2) & 7;
    const int bh = tid >> 5;
    const int j  = (blk << 3) + jl;

    const float bhr = bhh[j], bhz = bhh[Hsz + j], bhn = bhh[2 * Hsz + j];
    const float4* pwr = (const float4*)(wr + (jl << 9)) + (q << 5);
    const float4* pwz = (const float4*)(wz + (jl << 9)) + (q << 5);
    const float4* pwn = (const float4*)(wn + (jl << 9)) + (q << 5);
    const float4* ph0 = (const float4*)(hh + (bh << 9)) + (q << 5);
    const float4* ph1 = (const float4*)(hh + ((bh + 4) << 9)) + (q << 5);

    unsigned target = 0;

    for (int t = 0; t < Lsz; t++) {
        float ar0 = 0, az0 = 0, an0 = 0, ar1 = 0, az1 = 0, an1 = 0;
        #pragma unroll 4
        for (int i = 0; i < 32; i++) {
            float4 w4r = pwr[i], w4z = pwz[i], w4n = pwn[i];
            float4 hA = ph0[i], hB = ph1[i];
            ar0 += w4r.x*hA.x + w4r.y*hA.y + w4r.z*hA.z + w4r.w*hA.w;
            az0 += w4z.x*hA.x + w4z.y*hA.y + w4z.z*hA.z + w4z.w*hA.w;
            an0 += w4n.x*hA.x + w4n.y*hA.y + w4n.z*hA.z + w4n.w*hA.w;
            ar1 += w4r.x*hB.x + w4r.y*hB.y + w4r.z*hB.z + w4r.w*hB.w;
            az1 += w4z.x*hB.x + w4z.y*hB.y + w4z.z*hB.z + w4z.w*hB.w;
            an1 += w4n.x*hB.x + w4n.y*hB.y + w4n.z*hB.z + w4n.w*hB.w;
        }
        #pragma unroll
        for (int off = 1; off <= 2; off <<= 1) {
            ar0 += __shfl_xor_sync(0xffffffffu, ar0, off);
            az0 += __shfl_xor_sync(0xffffffffu, az0, off);
            an0 += __shfl_xor_sync(0xffffffffu, an0, off);
            ar1 += __shfl_xor_sync(0xffffffffu, ar1, off);
            az1 += __shfl_xor_sync(0xffffffffu, az1, off);
            an1 += __shfl_xor_sync(0xffffffffu, an1, off);
        }
        if (q == 0) {
            #pragma unroll
            for (int half = 0; half < 2; half++) {
                int b = bh + (half ? 4 : 0);
                float ghr = half ? ar1 : ar0;
                float ghz = half ? az1 : az0;
                float ghn = half ? an1 : an0;
                long gbase = (long)((b << 7) + t) * (3 * Hsz);
                float ir = gi[gbase + j];
                float iz = gi[gbase + Hsz + j];
                float in_ = gi[gbase + 2 * Hsz + j];
                float r = 1.0f / (1.0f + expf(-(ir + ghr + bhr)));
                float z = 1.0f / (1.0f + expf(-(iz + ghz + bhz)));
                float n = tanhf(in_ + r * (ghn + bhn));
                float hold = hh[(b << 9) + j];
                float hnew = (1.0f - z) * n + z * hold;
                out[(long)((b << 7) + t) * Hsz + j] = hnew;
                hglob[((t + 1) & 1) * (Bsz * Hsz) + (b << 9) + j] = hnew;
            }
        }
        __threadfence();
        __syncthreads();
        if (tid == 0) {
            atomicAdd(bar, 1u);
            target += GRU_BLOCKS;
            volatile unsigned* vb = bar;
            while (*vb < target) { }
        }
        __syncthreads();
        __threadfence();
        const float4* src = (const float4*)(hglob + ((t + 1) & 1) * (Bsz * Hsz));
        for (int f = tid; f < 1024; f += GRU_THREADS)
            ((float4*)hh)[f] = __ldcg(src + f);
        __syncthreads();
    }
}

// ---------------- copy-attention context (alphas independent of i) -------
__global__ void copy_ctx_kernel(const float* __restrict__ enc_out,
                                const int* __restrict__ enc_in,
                                const float* __restrict__ copyW,
                                float* __restrict__ ctx) {
    __shared__ float4 we4[Hsz / 4];
    __shared__ float alpha[Lsz];
    __shared__ float rbuf[Lsz];
    int b = blockIdx.x, tid = threadIdx.x;
    we4[tid] = ((const float4*)copyW)[tid];
    __syncthreads();
    const float4* row = (const float4*)(enc_out + (long)(b * Lsz + tid) * Hsz);
    float s = 0.0f;
    for (int k = 0; k < Hsz / 4; k++) {
        float4 r = row[k], w = we4[k];
        s += r.x*w.x + r.y*w.y + r.z*w.z + r.w*w.w;
    }
    if (enc_in[b * Lsz + tid] == 0) s -= 1000.0f;
    rbuf[tid] = s; __syncthreads();
    for (int st = 64; st > 0; st >>= 1) {
        if (tid < st) rbuf[tid] = fmaxf(rbuf[tid], rbuf[tid + st]);
        __syncthreads();
    }
    float m = rbuf[0]; __syncthreads();
    float e = expf(s - m);
    rbuf[tid] = e; __syncthreads();
    for (int st = 64; st > 0; st >>= 1) {
        if (tid < st) rbuf[tid] += rbuf[tid + st];
        __syncthreads();
    }
    alpha[tid] = e / rbuf[0];
    __syncthreads();
    float a0 = 0, a1 = 0, a2 = 0, a3 = 0;
    const float* E = enc_out + (long)b * Lsz * Hsz;
    for (int jj = 0; jj < Lsz; jj++) {
        float a = alpha[jj];
        const float* er = E + jj * Hsz;
        a0 += a * er[tid];       a1 += a * er[tid + 128];
        a2 += a * er[tid + 256]; a3 += a * er[tid + 384];
    }
    float* o = ctx + (long)b * Hsz;
    o[tid] = a0; o[tid + 128] = a1; o[tid + 256] = a2; o[tid + 384] = a3;
}

// ---------------- mix gate ------------------------------------------------
__global__ void mix_kernel(const float* __restrict__ gruout,
                           const float* __restrict__ ctx,
                           const float* __restrict__ emb,
                           const float* __restrict__ dgW,
                           const float* __restrict__ dgb,
                           float* __restrict__ mixbuf) {
    int row = blockIdx.x;
    int b = row >> 7;
    int tid = threadIdx.x;
    const float* g = gruout + (long)row * Hsz;
    const float* c = ctx + (long)b * Hsz;
    const float* e = emb + (long)row * Hsz;
    float s = 0.0f;
    for (int k = tid; k < Hsz; k += 128)
        s += g[k] * dgW[k] + c[k] * dgW[Hsz + k] + e[k] * dgW[2 * Hsz + k];
    __shared__ float rbuf[128];
    rbuf[tid] = s; __syncthreads();
    for (int st = 64; st > 0; st >>= 1) {
        if (tid < st) rbuf[tid] += rbuf[tid + st];
        __syncthreads();
    }
    if (tid == 0) mixbuf[row] = 1.0f / (1.0f + expf(-(rbuf[0] + dgb[0])));
}

// ---------------- final: online softmax over V + pointer mix (in place) --
__global__ void softmax_mix_kernel(float* __restrict__ prob,
                                   const float* __restrict__ mixbuf,
                                   const int* __restrict__ enc_in) {
    int row = blockIdx.x;
    int tid = threadIdx.x;   // 256
    float* p = prob + (long)row * Vsz;
    // pass 1: online (max, sum) per thread over float4 stream
    float m = -1e30f, s = 0.0f;
    const float4* p4 = (const float4*)p;
    for (int v = tid; v < Vsz / 4; v += 256) {
        float4 x = p4[v];
        float lm = fmaxf(fmaxf(x.x, x.y), fmaxf(x.z, x.w));
        if (lm > m) { s *= expf(m - lm); m = lm; }
        s += expf(x.x - m) + expf(x.y - m) + expf(x.z - m) + expf(x.w - m);
    }
    __shared__ float rm[256], rs[256];
    rm[tid] = m; rs[tid] = s; __syncthreads();
    for (int st = 128; st > 0; st >>= 1) {
        if (tid < st) {
            float m2 = rm[tid + st], s2 = rs[tid + st];
            float M = fmaxf(rm[tid], m2);
            rs[tid] = rs[tid] * expf(rm[tid] - M) + s2 * expf(m2 - M);
            rm[tid] = M;
        }
        __syncthreads();
    }
    float M = rm[0], S = rs[0];
    float mix = mixbuf[row];
    float inv = mix / S;
    float add = 1.0f - mix;      // row_sum of alphas == 1
    int tok = enc_in[row];
    float4* w4 = (float4*)p;
    for (int v = tid; v < Vsz / 4; v += 256) {
        float4 x = w4[v];
        x.x = expf(x.x - M) * inv;
        x.y = expf(x.y - M) * inv;
        x.z = expf(x.z - M) * inv;
        x.w = expf(x.w - M) * inv;
        int base = v * 4;
        if (tok >= base && tok < base + 4) {
            if (tok == base)     x.x += add;
            else if (tok == base + 1) x.y += add;
            else if (tok == base + 2) x.z += add;
            else                 x.w += add;
        }
        w4[v] = x;
    }
}

// ---------------- launch --------------------------------------------------
extern "C" void kernel_launch(void* const* d_in, const int* in_sizes, int n_in,
                              void* d_out, int out_size) {
    (void)in_sizes; (void)n_in; (void)out_size;
    const int*   input_   = (const int*)d_in[0];
    const int*   enc_in   = (const int*)d_in[1];
    const float* enc_hid  = (const float*)d_in[2];
    const float* enc_out  = (const float*)d_in[3];
    const float* emb_tab  = (const float*)d_in[4];
    const float* attn_W   = (const float*)d_in[5];
    const float* comb_W   = (const float*)d_in[7];
    const float* comb_b   = (const float*)d_in[8];
    const float* gru_Wih  = (const float*)d_in[9];
    const float* gru_Whh  = (const float*)d_in[10];
    const float* gru_bih  = (const float*)d_in[11];
    const float* gru_bhh  = (const float*)d_in[12];
    const float* out_W    = (const float*)d_in[13];
    const float* out_b    = (const float*)d_in[14];
    const float* dogen_W  = (const float*)d_in[15];
    const float* dogen_b  = (const float*)d_in[16];
    const float* copy_W   = (const float*)d_in[17];

    float* out   = (float*)d_out;
    float* prob  = out;
    float* attnw = out + PROB_ELEMS;

    float* sc = nullptr;
    cudaGetSymbolAddress((void**)&sc, d_scratch);
    float* emb     = sc + OFF_EMB;
    float* sattn   = sc + OFF_SATTN;
    float* attnapp = sc + OFF_ATTNAPP;
    float* xbuf    = sc + OFF_X;
    float* gibuf   = sc + OFF_GI;
    float* gruout  = sc + OFF_GRUOUT;
    float* ctx     = sc + OFF_CTX;
    float* mixb    = sc + OFF_MIX;
    float* hglob   = sc + OFF_HGLOB;
    unsigned* bar  = (unsigned*)(sc + OFF_BAR);

    const int gru_smem = (24 * Hsz + Bsz * Hsz) * (int)sizeof(float);
    cudaFuncSetAttribute(gru_kernel, cudaFuncAttributeMaxDynamicSharedMemorySize, gru_smem);

    // 1. embedding gather
    gather_kernel<<<NROWS, 128>>>(input_, emb_tab, emb);
    // 2. attn logits (emb part only; h0/attn_b cancel in axis=1 softmax)
    sgemm128_kernel<<<dim3(Lsz / BN, NROWS / BM), 256>>>(
        emb, Hsz, attn_W, 2 * Hsz, sattn, Lsz, Hsz, nullptr, 0);
    // 3. softmax over i -> attn_weights (output tail)
    attn_softmax_kernel<<<Bsz, Lsz>>>(sattn, attnw);
    // 4. attn_applied
    attn_applied_kernel<<<NROWS, 128>>>(attnw, enc_out, attnapp);
    // 5. comb: x = relu(emb@W1^T + attnapp@W2^T + b)
    sgemm128_kernel<<<dim3(Hsz / BN, NROWS / BM), 256>>>(
        emb, Hsz, comb_W, 2 * Hsz, xbuf, Hsz, Hsz, nullptr, 0);
    sgemm128_kernel<<<dim3(Hsz / BN, NROWS / BM), 256>>>(
        attnapp, Hsz, comb_W + Hsz, 2 * Hsz, xbuf, Hsz, Hsz, comb_b,
        FLAG_ACCUM | FLAG_BIAS | FLAG_RELU);
    // 6. gi = x @ Wih^T + bih
    sgemm128_kernel<<<dim3(3 * Hsz / BN, NROWS / BM), 256>>>(
        xbuf, Hsz, gru_Wih, Hsz, gibuf, 3 * Hsz, Hsz, gru_bih, FLAG_BIAS);
    // 7. GRU (persistent cooperative)
    reset_bar_kernel<<<1, 1>>>(bar);
    gru_kernel<<<GRU_BLOCKS, GRU_THREADS, gru_smem>>>(
        gru_Whh, gru_bhh, gibuf, enc_hid, gruout, hglob, bar);
    // 8. output logits GEMM (1024 x 32000 x 512) straight into d_out
    sgemm128_kernel<<<dim3(Vsz / BN, NROWS / BM), 256>>>(
        gruout, Hsz, out_W, Hsz, prob, Vsz, Hsz, out_b, FLAG_BIAS);
    // 9. copy-attention context (alphas i-independent)
    copy_ctx_kernel<<<Bsz, Lsz>>>(enc_out, enc_in, copy_W, ctx);
    // 10. mix gate
    mix_kernel<<<NROWS, 128>>>(gruout, ctx, emb, dogen_W, dogen_b, mixb);
    // 11. online softmax over V + pointer mix, in place
    softmax_mix_kernel<<<NROWS, 256>>>(prob, mixb, enc_in);
}